// round 12
// baseline (speedup 1.0000x reference)
#include <cuda_runtime.h>

// Problem constants (fixed shapes per reference setup_inputs)
#define N_IN   65536
#define BATCH  128
#define N_OUTP 65536
#define M_SAMP 131072   // N_OUT * degree, degree = 2

// Scratch (device globals: allocation inside kernel_launch is forbidden)
__device__ __align__(16) float g_actT[(size_t)N_IN * BATCH];  // 32 MB transposed, clipped
__device__ int2 g_pairs[M_SAMP];                 // per-sample: {idx*32 (f4 row), bitcast(w)}

// Replicate jnp.linspace(0,1,65536, float32): x[i] = fl(i * fl(1/65535)), x[last]=1.0
__device__ __forceinline__ float gridx(int i) {
    return (i == N_IN - 1) ? 1.0f : (float)i * (1.0f / 65535.0f);
}

// ---------------------------------------------------------------------------
// Kernel 1 (fused): sampling + clip/transpose. float4 both ways via XOR-swizzle.
// Grid (512, 4), 256 threads. Block tile: n 128 x b 32. 64 samples/block.
// ---------------------------------------------------------------------------
__global__ void __launch_bounds__(256) prep_kernel(const float* __restrict__ act,
                                                   const float* __restrict__ sp_in) {
    // logical (b, c4) lives at tile4[b][c4 ^ ((b>>2) & 7)]
    __shared__ __align__(16) float4 tile4[32][32];   // 16 KB
    const int tid = threadIdx.x;
    const int n0  = blockIdx.x * 128;
    const int b0  = blockIdx.y * 32;

    // --- sampling: 64 samples per block ---
    if (tid < 64) {
        int m = (blockIdx.y * gridDim.x + blockIdx.x) * 64 + tid;
        float sp = sp_in[m];
        sp = fminf(fmaxf(sp, 0.0f), 1.0f);
        int i = (int)(sp * 65535.0f);
        i = max(0, min(i, N_IN - 2));
        // Exact searchsorted-left fix-up: largest i with x[i] < sp (clamped)
        while (i > 0 && gridx(i) >= sp) --i;
        while (i < N_IN - 2 && gridx(i + 1) < sp) ++i;
        float xi = gridx(i);
        float dx = gridx(i + 1) - xi;
        float w  = (sp - xi) / (dx + 1e-8f);
        g_pairs[m] = make_int2(i * 32, __float_as_int(w));  // pre-scaled float4 row
    }

    // --- load: thread (tx=c4 0..31, ty 0..7) reads float4 along n ---
    const int tx = tid & 31;
    const int ty = tid >> 5;
    const float4* a4 = (const float4*)act;   // row stride N_IN/4 = 16384
#pragma unroll
    for (int j = 0; j < 4; ++j) {
        int brow = ty + 8 * j;               // local b: 0..31
        float4 v = __ldcs(&a4[(size_t)(b0 + brow) * 16384 + (n0 >> 2) + tx]);
        v.x = __saturatef(v.x);
        v.y = __saturatef(v.y);
        v.z = __saturatef(v.z);
        v.w = __saturatef(v.w);
        tile4[brow][tx ^ ((brow >> 2) & 7)] = v;   // STS.128, conflict-free
    }
    __syncthreads();

    // --- store: thread (cx 0..7, n4 0..31) does a 4x4 micro-transpose ---
    const int cx = tid & 7;
    const int n4 = tid >> 3;
    float4 m0 = tile4[4 * cx + 0][n4 ^ cx];   // LDS.128, conflict-free
    float4 m1 = tile4[4 * cx + 1][n4 ^ cx];
    float4 m2 = tile4[4 * cx + 2][n4 ^ cx];
    float4 m3 = tile4[4 * cx + 3][n4 ^ cx];

    float4* t4 = (float4*)g_actT;             // row stride BATCH/4 = 32
    size_t base = (size_t)(n0 + 4 * n4) * 32 + (b0 >> 2) + cx;
    t4[base + 0 * 32] = make_float4(m0.x, m1.x, m2.x, m3.x);
    t4[base + 1 * 32] = make_float4(m0.y, m1.y, m2.y, m3.y);
    t4[base + 2 * 32] = make_float4(m0.z, m1.z, m2.z, m3.z);
    t4[base + 3 * 32] = make_float4(m0.w, m1.w, m2.w, m3.w);
}

// ---------------------------------------------------------------------------
// Kernel 2: main — fully warp-autonomous. No smem, no __syncthreads.
// Warp w of each block owns 4 consecutive n. Lane l covers batches 4l..4l+3.
// 16 independent LDG.128 per warp-tile (8KB MLP), compute, 4x4 in-register
// transpose, 16B STG.128 per lane per batch row (L2 merges neighboring-n
// halves into full 32B sectors; DRAM write traffic stays ~33.5 MB).
// ---------------------------------------------------------------------------
__global__ void __launch_bounds__(256) main_kernel(float* __restrict__ out) {
    const int tid = threadIdx.x;
    const int w   = tid >> 5;            // warp 0..7
    const int l   = tid & 31;            // lane
    const int nw  = blockIdx.x * 32 + w * 4;   // first of this warp's 4 n

    const int4*   __restrict__ pairs = (const int4*)g_pairs;  // {i0*32,w0,i1*32,w1}
    const float4* __restrict__ actT4 = (const float4*)g_actT; // row stride 32 f4

    // uniform metadata (broadcast loads: one sector per int4 across the warp)
    int4 s[4];
#pragma unroll
    for (int k = 0; k < 4; ++k) s[k] = __ldg(&pairs[nw + k]);

    // gather phase: all 16 loads issued before any consumption
    float4 A[16];
#pragma unroll
    for (int k = 0; k < 4; ++k) {
        const int r0 = s[k].x;           // pre-scaled float4 row of i0
        const int r1 = s[k].z;           // pre-scaled float4 row of i1
        A[4 * k + 0] = __ldg(&actT4[r0 + l]);
        A[4 * k + 1] = __ldg(&actT4[r0 + 32 + l]);
        A[4 * k + 2] = __ldg(&actT4[r1 + l]);
        A[4 * k + 3] = __ldg(&actT4[r1 + 32 + l]);
    }

    // compute: lerp + fuzzy-NAND pair product (same op order as reference)
    float res[4][4];                     // [n-offset][batch-component]
#pragma unroll
    for (int k = 0; k < 4; ++k) {
        const float w0 = __int_as_float(s[k].y);
        const float w1 = __int_as_float(s[k].w);
        const float4 a00 = A[4 * k + 0], a01 = A[4 * k + 1];
        const float4 a10 = A[4 * k + 2], a11 = A[4 * k + 3];
        res[k][0] = (1.0f - fmaf(a01.x - a00.x, w0, a00.x)) * (1.0f - fmaf(a11.x - a10.x, w1, a10.x));
        res[k][1] = (1.0f - fmaf(a01.y - a00.y, w0, a00.y)) * (1.0f - fmaf(a11.y - a10.y, w1, a10.y));
        res[k][2] = (1.0f - fmaf(a01.z - a00.z, w0, a00.z)) * (1.0f - fmaf(a11.z - a10.z, w1, a10.z));
        res[k][3] = (1.0f - fmaf(a01.w - a00.w, w0, a00.w)) * (1.0f - fmaf(a11.w - a10.w, w1, a10.w));
    }

    // epilogue: in-register 4x4 transpose, float4-over-n stores
#pragma unroll
    for (int c = 0; c < 4; ++c) {
        float4 v = make_float4(res[0][c], res[1][c], res[2][c], res[3][c]);
        float4* dst = (float4*)&out[(size_t)(4 * l + c) * N_OUTP + nw];
        __stcs(dst, v);
    }
}

// ---------------------------------------------------------------------------
extern "C" void kernel_launch(void* const* d_in, const int* in_sizes, int n_in,
                              void* d_out, int out_size) {
    const float* act = (const float*)d_in[0];   // (128, 65536) f32
    const float* sp  = (const float*)d_in[1];   // (65536, 2, 1) f32
    float* out       = (float*)d_out;           // (128, 65536) f32

    prep_kernel<<<dim3(N_IN / 128, BATCH / 32), 256>>>(act, sp);
    main_kernel<<<N_OUTP / 32, 256>>>(out);
}